// round 3
// baseline (speedup 1.0000x reference)
#include <cuda_runtime.h>
#include <cstdint>
#include <cstddef>

#define BB 64
#define TT 256
#define EE 256
#define UU 512
#define GG 2048
#define NBLK 128
#define SH 516
#define SMEM_SCAN ((64 * SH + 32 * SH) * 4)

// Device-global scratch (allocation-guard safe).
__device__ float    g_xproj[(size_t)2 * TT * BB * GG];   // 256 MB [dir][t][b][4U]
__device__ float    g_h[2 * 2 * BB * UU];                // [parity][dir][b][u]
__device__ unsigned g_bar[TT];

__global__ void reset_kernel() { g_bar[threadIdx.x] = 0u; }

// ---------------------------------------------------------------------------
// x_proj[dir][t][b][g] = emb[x[b,t]] @ W_dir + b_dir
// 128x128 tile, BK=16, 256 threads, 8x8 per-thread tile. row r = t*64+b.
// ---------------------------------------------------------------------------
__global__ void __launch_bounds__(256, 2) xproj_kernel(
    const int* __restrict__ x, const float* __restrict__ emb,
    const float* __restrict__ W_f, const float* __restrict__ b_f,
    const float* __restrict__ W_b, const float* __restrict__ b_b)
{
    const int dir = blockIdx.z;
    const float* Wm   = dir ? W_b : W_f;
    const float* bias = dir ? b_b : b_f;
    const int n0 = blockIdx.x << 7;
    const int m0 = blockIdx.y << 7;

    __shared__ float As[16][132];
    __shared__ float Ws[16][132];
    __shared__ int   toks[128];

    const int tid = threadIdx.x;
    if (tid < 128) {
        int r = m0 + tid;
        toks[tid] = x[(r & 63) * TT + (r >> 6)];
    }
    __syncthreads();

    float acc[8][8] = {};
    const int ty = tid >> 4, tx = tid & 15;

    for (int k0 = 0; k0 < EE; k0 += 16) {
        #pragma unroll
        for (int l = 0; l < 2; l++) {
            int idx = (l << 8) + tid;
            int m = idx >> 2, kv = idx & 3;
            float4 e4 = *(const float4*)&emb[(size_t)toks[m] * EE + k0 + (kv << 2)];
            As[(kv << 2) + 0][m] = e4.x;
            As[(kv << 2) + 1][m] = e4.y;
            As[(kv << 2) + 2][m] = e4.z;
            As[(kv << 2) + 3][m] = e4.w;
        }
        #pragma unroll
        for (int l = 0; l < 2; l++) {
            int idx = (l << 8) + tid;
            int kk = idx >> 5, nv = idx & 31;
            *(float4*)&Ws[kk][nv << 2] =
                *(const float4*)&Wm[(size_t)(k0 + kk) * GG + n0 + (nv << 2)];
        }
        __syncthreads();
        #pragma unroll 4
        for (int kk = 0; kk < 16; kk++) {
            float a[8], w[8];
            *(float4*)&a[0] = *(const float4*)&As[kk][ty << 2];
            *(float4*)&a[4] = *(const float4*)&As[kk][64 + (ty << 2)];
            *(float4*)&w[0] = *(const float4*)&Ws[kk][tx << 2];
            *(float4*)&w[4] = *(const float4*)&Ws[kk][64 + (tx << 2)];
            #pragma unroll
            for (int i = 0; i < 8; i++)
                #pragma unroll
                for (int j = 0; j < 8; j++) acc[i][j] += a[i] * w[j];
        }
        __syncthreads();
    }

    float bv[8];
    *(float4*)&bv[0] = *(const float4*)&bias[n0 + (tx << 2)];
    *(float4*)&bv[4] = *(const float4*)&bias[n0 + 64 + (tx << 2)];
    float* outp = g_xproj + (size_t)dir * TT * BB * GG;
    #pragma unroll
    for (int i = 0; i < 8; i++) {
        int r = m0 + ((i < 4) ? ((ty << 2) + i) : (64 + (ty << 2) + i - 4));
        float4 v0, v1;
        v0.x = acc[i][0] + bv[0]; v0.y = acc[i][1] + bv[1];
        v0.z = acc[i][2] + bv[2]; v0.w = acc[i][3] + bv[3];
        v1.x = acc[i][4] + bv[4]; v1.y = acc[i][5] + bv[5];
        v1.z = acc[i][6] + bv[6]; v1.w = acc[i][7] + bv[7];
        *(float4*)&outp[(size_t)r * GG + n0 + (tx << 2)]      = v0;
        *(float4*)&outp[(size_t)r * GG + n0 + 64 + (tx << 2)] = v1;
    }
}

// ---------------------------------------------------------------------------
// Persistent bidirectional LSTM scan. 128 CTAs x 256 threads.
// CTA = (dir, 8 hidden units) -> 32 z-columns. Per step:
//   stage h[64][512] -> smem, z += h @ R_slice (4 k-groups, 8x4 reg tiles),
//   smem reduce, gate update (2 (b,u) pairs/thread), grid barrier.
// ---------------------------------------------------------------------------
__global__ void __launch_bounds__(256, 1) scan_kernel(
    const int* __restrict__ x,
    const float* __restrict__ R_f,
    const float* __restrict__ R_b,
    float* __restrict__ out)
{
    extern __shared__ float sm[];
    float* hs = sm;            // [64][SH]
    float* Rs = sm + 64 * SH;  // [32][SH]
    float* zr = sm;            // alias: partials, idx = b*132 + c*4 + grp

    const int tid = threadIdx.x;
    const int dir = blockIdx.x >> 6;
    const int u0  = (blockIdx.x & 63) << 3;
    const float* Rm = dir ? R_b : R_f;
    const float* xp = g_xproj + (size_t)dir * TT * BB * GG;

    // Persistent R slice: Rs[c][k], c = gate*8+uu -> R[k][gate*512 + u0+uu]
    #pragma unroll 4
    for (int l = 0; l < 64; l++) {
        int idx = (l << 8) + tid;
        int c = idx & 31, k = idx >> 5;
        Rs[c * SH + k] = Rm[(size_t)k * GG + (c >> 3) * UU + u0 + (c & 7)];
    }

    const int grp = tid >> 6;          // k-group (128 k each)
    const int ty  = (tid >> 3) & 7;    // row base (rows ty+8i)
    const int tx  = tid & 7;           // col base (cols tx+8j)
    const int kb  = grp << 7;

    const int b  = tid >> 2;           // update ownership: (b, uu), (b, uu+1)
    const int uu = (tid & 3) << 1;
    float c0 = 0.f, c1 = 0.f, h0 = 0.f, h1 = 0.f;

    for (int s = 0; s < TT; s++) {
        float s0[4] = {}, s1[4] = {};
        if (s) {
            // Stage previous h (parity (s-1)&1)
            const float4* hsrc =
                (const float4*)(g_h + ((((s + 1) & 1) * 2 + dir) * BB * UU));
            #pragma unroll
            for (int l = 0; l < 32; l++) {
                int f = (l << 8) + tid;
                *(float4*)&hs[(f >> 7) * SH + ((f & 127) << 2)] = hsrc[f];
            }
            __syncthreads();

            float acc[8][4] = {};
            #pragma unroll 2
            for (int kk = 0; kk < 128; kk += 4) {
                float4 rv[4];
                #pragma unroll
                for (int j = 0; j < 4; j++)
                    rv[j] = *(const float4*)&Rs[(tx + (j << 3)) * SH + kb + kk];
                #pragma unroll
                for (int i = 0; i < 8; i++) {
                    float4 hv = *(const float4*)&hs[(ty + (i << 3)) * SH + kb + kk];
                    #pragma unroll
                    for (int j = 0; j < 4; j++)
                        acc[i][j] += hv.x * rv[j].x + hv.y * rv[j].y +
                                     hv.z * rv[j].z + hv.w * rv[j].w;
                }
            }
            __syncthreads();
            #pragma unroll
            for (int i = 0; i < 8; i++)
                #pragma unroll
                for (int j = 0; j < 4; j++)
                    zr[(ty + (i << 3)) * 132 + ((tx + (j << 3)) << 2) + grp] = acc[i][j];
            __syncthreads();

            #pragma unroll
            for (int g = 0; g < 4; g++) {
                float4 v0 = *(const float4*)&zr[b * 132 + (((g << 3) + uu) << 2)];
                float4 v1 = *(const float4*)&zr[b * 132 + (((g << 3) + uu + 1) << 2)];
                s0[g] = v0.x + v0.y + v0.z + v0.w;
                s1[g] = v1.x + v1.y + v1.z + v1.w;
            }
        }

        const int t = dir ? (TT - 1 - s) : s;
        const int m = x[b * TT + t] != 0;
        const float* xpt = xp + ((size_t)t * BB + b) * GG + u0 + uu;
        float z0[4], z1[4];
        #pragma unroll
        for (int g = 0; g < 4; g++) {
            float2 xg = *(const float2*)(xpt + (g << 9));
            z0[g] = xg.x + s0[g];
            z1[g] = xg.y + s1[g];
        }
        float i0 = tanhf(z0[0]), f0 = tanhf(z0[1]), g0 = tanhf(z0[2]), o0 = tanhf(z0[3]);
        float i1 = tanhf(z1[0]), f1 = tanhf(z1[1]), g1 = tanhf(z1[2]), o1 = tanhf(z1[3]);
        float cn0 = f0 * c0 + i0 * g0;
        float cn1 = f1 * c1 + i1 * g1;
        float hn0 = o0 * tanhf(cn0);
        float hn1 = o1 * tanhf(cn1);
        if (m) { c0 = cn0; h0 = hn0; c1 = cn1; h1 = hn1; }

        *(float2*)(g_h + (((s & 1) * 2 + dir) * BB * UU) + b * UU + u0 + uu) =
            make_float2(h0, h1);
        *(float2*)(out + (((size_t)(b * TT + t)) << 10) + (dir << 9) + u0 + uu) =
            make_float2(h0, h1);
        if (dir && s == TT - 1)
            *(float2*)(out + (size_t)BB * TT * 1024 + b * UU + u0 + uu) =
                make_float2(h0, h1);

        __syncthreads();
        if (s < TT - 1) {
            if (tid == 0) {
                asm volatile("red.release.gpu.add.u32 [%0], 1;"
                             :: "l"(&g_bar[s]) : "memory");
                unsigned cnt;
                do {
                    asm volatile("ld.acquire.gpu.u32 %0, [%1];"
                                 : "=r"(cnt) : "l"(&g_bar[s]) : "memory");
                } while (cnt < NBLK);
            }
            __syncthreads();
        }
    }
}

extern "C" void kernel_launch(void* const* d_in, const int* in_sizes, int n_in,
                              void* d_out, int out_size) {
    const int*   x   = (const int*)d_in[0];
    const float* emb = (const float*)d_in[1];
    const float* W_f = (const float*)d_in[2];
    const float* R_f = (const float*)d_in[3];
    const float* b_f = (const float*)d_in[4];
    const float* W_b = (const float*)d_in[5];
    const float* R_b = (const float*)d_in[6];
    const float* b_b = (const float*)d_in[7];
    float* out = (float*)d_out;

    static bool attr_set = false;
    if (!attr_set) {
        cudaFuncSetAttribute(scan_kernel,
                             cudaFuncAttributeMaxDynamicSharedMemorySize, SMEM_SCAN);
        attr_set = true;
    }

    reset_kernel<<<1, TT>>>();
    dim3 gx(GG / 128, (TT * BB) / 128, 2);
    xproj_kernel<<<gx, 256>>>(x, emb, W_f, b_f, W_b, b_b);
    scan_kernel<<<NBLK, 256, SMEM_SCAN>>>(x, R_f, R_b, out);
}

// round 4
// speedup vs baseline: 1.0428x; 1.0428x over previous
#include <cuda_runtime.h>
#include <cstdint>
#include <cstddef>

#define BB 64
#define TT 256
#define EE 256
#define UU 512
#define GG 2048
#define NBLK 128
#define SH 516
#define RT_OFF (32 * SH)
#define SMEM_SCAN ((32 * SH + 512 * 64) * 4)

typedef unsigned long long ull;

__device__ __forceinline__ ull pack_dup(float x) {
    ull r;
    asm("mov.b64 %0, {%1, %1};" : "=l"(r) : "f"(x));
    return r;
}
__device__ __forceinline__ void ffma2(ull& acc, ull a, ull b) {
    asm("fma.rn.f32x2 %0, %1, %2, %0;" : "+l"(acc) : "l"(a), "l"(b));
}
__device__ __forceinline__ float2 unpk(ull v) {
    float2 f;
    asm("mov.b64 {%0, %1}, %2;" : "=f"(f.x), "=f"(f.y) : "l"(v));
    return f;
}

// Device-global scratch (allocation-guard safe).
__device__ float    g_xproj[(size_t)2 * TT * BB * GG];   // [dir][t][b][4U]
__device__ float    g_h[2 * 2 * BB * UU];                // [parity][dir][b][u]
__device__ unsigned g_bar[TT];

__global__ void reset_kernel() { g_bar[threadIdx.x] = 0u; }

// ---------------------------------------------------------------------------
// x_proj[dir][t][b][g] = emb[x[b,t]] @ W_dir + b_dir
// 128x128 tile, BK=16, 256 threads, 8x8 per-thread tile via f32x2 FMA.
// ---------------------------------------------------------------------------
__global__ void __launch_bounds__(256, 2) xproj_kernel(
    const int* __restrict__ x, const float* __restrict__ emb,
    const float* __restrict__ W_f, const float* __restrict__ b_f,
    const float* __restrict__ W_b, const float* __restrict__ b_b)
{
    const int dir = blockIdx.z;
    const float* Wm   = dir ? W_b : W_f;
    const float* bias = dir ? b_b : b_f;
    const int n0 = blockIdx.x << 7;
    const int m0 = blockIdx.y << 7;

    __shared__ float As[16][132];
    __shared__ float Ws[16][132];
    __shared__ int   toks[128];

    const int tid = threadIdx.x;
    if (tid < 128) {
        int r = m0 + tid;
        toks[tid] = x[(r & 63) * TT + (r >> 6)];
    }
    __syncthreads();

    ull acc[8][4] = {};
    const int ty = tid >> 4, tx = tid & 15;

    for (int k0 = 0; k0 < EE; k0 += 16) {
        #pragma unroll
        for (int l = 0; l < 2; l++) {
            int idx = (l << 8) + tid;
            int m = idx >> 2, kv = idx & 3;
            float4 e4 = *(const float4*)&emb[(size_t)toks[m] * EE + k0 + (kv << 2)];
            As[(kv << 2) + 0][m] = e4.x;
            As[(kv << 2) + 1][m] = e4.y;
            As[(kv << 2) + 2][m] = e4.z;
            As[(kv << 2) + 3][m] = e4.w;
        }
        #pragma unroll
        for (int l = 0; l < 2; l++) {
            int idx = (l << 8) + tid;
            int kk = idx >> 5, nv = idx & 31;
            *(float4*)&Ws[kk][nv << 2] =
                *(const float4*)&Wm[(size_t)(k0 + kk) * GG + n0 + (nv << 2)];
        }
        __syncthreads();
        #pragma unroll 4
        for (int kk = 0; kk < 16; kk++) {
            float a[8];
            *(float4*)&a[0] = *(const float4*)&As[kk][ty << 2];
            *(float4*)&a[4] = *(const float4*)&As[kk][64 + (ty << 2)];
            ull w0 = *(const ull*)&Ws[kk][(tx << 2)];
            ull w1 = *(const ull*)&Ws[kk][(tx << 2) + 2];
            ull w2 = *(const ull*)&Ws[kk][64 + (tx << 2)];
            ull w3 = *(const ull*)&Ws[kk][64 + (tx << 2) + 2];
            #pragma unroll
            for (int i = 0; i < 8; i++) {
                ull ad = pack_dup(a[i]);
                ffma2(acc[i][0], ad, w0);
                ffma2(acc[i][1], ad, w1);
                ffma2(acc[i][2], ad, w2);
                ffma2(acc[i][3], ad, w3);
            }
        }
        __syncthreads();
    }

    float bv[8];
    *(float4*)&bv[0] = *(const float4*)&bias[n0 + (tx << 2)];
    *(float4*)&bv[4] = *(const float4*)&bias[n0 + 64 + (tx << 2)];
    float* outp = g_xproj + (size_t)dir * TT * BB * GG;
    #pragma unroll
    for (int i = 0; i < 8; i++) {
        int r = m0 + ((i < 4) ? ((ty << 2) + i) : (64 + (ty << 2) + i - 4));
        float2 p0 = unpk(acc[i][0]), p1 = unpk(acc[i][1]);
        float2 p2 = unpk(acc[i][2]), p3 = unpk(acc[i][3]);
        float4 v0, v1;
        v0.x = p0.x + bv[0]; v0.y = p0.y + bv[1];
        v0.z = p1.x + bv[2]; v0.w = p1.y + bv[3];
        v1.x = p2.x + bv[4]; v1.y = p2.y + bv[5];
        v1.z = p3.x + bv[6]; v1.w = p3.y + bv[7];
        *(float4*)&outp[(size_t)r * GG + n0 + (tx << 2)]      = v0;
        *(float4*)&outp[(size_t)r * GG + n0 + 64 + (tx << 2)] = v1;
    }
}

// ---------------------------------------------------------------------------
// Persistent bidirectional LSTM scan. 128 CTAs x 256 threads.
// CTA = (dir, 32 batch rows, 16 hidden units -> 64 z-cols). Per step:
//   stage h[32][512] -> smem, z += h @ R_slice (f32x2, 4 k-groups,
//   8x2-pair reg tiles), smem reduce, gate update, grid barrier.
// ---------------------------------------------------------------------------
__global__ void __launch_bounds__(256, 1) scan_kernel(
    const int* __restrict__ x,
    const float* __restrict__ R_f,
    const float* __restrict__ R_b,
    float* __restrict__ out)
{
    extern __shared__ float sm[];
    float* hs = sm;            // [32][SH]
    float* Rt = sm + RT_OFF;   // [512][64]  (k-major, col pairs contiguous)
    float* zr = sm;            // alias: [32][260] partials (c*4 + grp)

    const int tid = threadIdx.x;
    const int dir = blockIdx.x >> 6;
    const int rr  = blockIdx.x & 63;
    const int b0  = (rr >> 5) << 5;     // batch block (0 or 32)
    const int u0  = (rr & 31) << 4;     // 16 hidden units
    const float* Rm = dir ? R_b : R_f;
    const float* xp = g_xproj + (size_t)dir * TT * BB * GG;

    // Rt[k][c] = R[k][gate*512 + u0 + uu], c = gate*16 + uu
    #pragma unroll 4
    for (int l = 0; l < 128; l++) {
        int idx = (l << 8) + tid;
        int c = idx & 63, k = idx >> 6;
        Rt[k * 64 + c] = Rm[(size_t)k * GG + (c >> 4) * UU + u0 + (c & 15)];
    }

    const int grp = tid >> 6;           // k-group (128 k each)
    const int ty  = (tid >> 4) & 3;     // rows ty + 4i
    const int tx  = tid & 15;           // cols tx*4 .. tx*4+3 (2 pairs)
    const int kb  = grp << 7;

    const int bl = tid >> 3;            // epilogue: local batch, 2 units
    const int uu = (tid & 7) << 1;
    const int gb = b0 + bl;
    float c0 = 0.f, c1 = 0.f, h0 = 0.f, h1 = 0.f;

    for (int s = 0; s < TT; s++) {
        const int t = dir ? (TT - 1 - s) : s;
        const int m = x[gb * TT + t] != 0;

        // x_proj loads early (independent of h staging)
        const float* xpt = xp + ((size_t)t * BB + gb) * GG + u0 + uu;
        float2 xg[4];
        #pragma unroll
        for (int g = 0; g < 4; g++) xg[g] = *(const float2*)(xpt + (g << 9));

        float s0[4] = {}, s1[4] = {};
        if (s) {
            // Stage previous h rows [b0, b0+32) (parity (s-1)&1)
            const float4* hsrc = (const float4*)
                (g_h + ((((s + 1) & 1) * 2 + dir) * BB + b0) * UU);
            #pragma unroll
            for (int l = 0; l < 16; l++) {
                int f = (l << 8) + tid;
                *(float4*)&hs[(f >> 7) * SH + ((f & 127) << 2)] = hsrc[f];
            }
            __syncthreads();

            ull acc[8][2] = {};
            #pragma unroll 1
            for (int kk = 0; kk < 128; kk += 4) {
                float4 hv[8];
                #pragma unroll
                for (int i = 0; i < 8; i++)
                    hv[i] = *(const float4*)&hs[(ty + (i << 2)) * SH + kb + kk];
                #pragma unroll
                for (int k = 0; k < 4; k++) {
                    ull rv0 = *(const ull*)&Rt[(kb + kk + k) * 64 + (tx << 2)];
                    ull rv1 = *(const ull*)&Rt[(kb + kk + k) * 64 + (tx << 2) + 2];
                    #pragma unroll
                    for (int i = 0; i < 8; i++) {
                        float h = (k == 0) ? hv[i].x : (k == 1) ? hv[i].y
                                 : (k == 2) ? hv[i].z : hv[i].w;
                        ull hd = pack_dup(h);
                        ffma2(acc[i][0], hd, rv0);
                        ffma2(acc[i][1], hd, rv1);
                    }
                }
            }
            __syncthreads();
            #pragma unroll
            for (int i = 0; i < 8; i++)
                #pragma unroll
                for (int j = 0; j < 2; j++) {
                    float2 p = unpk(acc[i][j]);
                    int row = ty + (i << 2);
                    int c = (tx << 2) + (j << 1);
                    zr[row * 260 + (c << 2) + grp]       = p.x;
                    zr[row * 260 + ((c + 1) << 2) + grp] = p.y;
                }
            __syncthreads();

            #pragma unroll
            for (int g = 0; g < 4; g++) {
                float4 v0 = *(const float4*)&zr[bl * 260 + (((g << 4) + uu) << 2)];
                float4 v1 = *(const float4*)&zr[bl * 260 + (((g << 4) + uu + 1) << 2)];
                s0[g] = v0.x + v0.y + v0.z + v0.w;
                s1[g] = v1.x + v1.y + v1.z + v1.w;
            }
        }

        float z0[4], z1[4];
        #pragma unroll
        for (int g = 0; g < 4; g++) {
            z0[g] = xg[g].x + s0[g];
            z1[g] = xg[g].y + s1[g];
        }
        float i0 = tanhf(z0[0]), f0 = tanhf(z0[1]), g0 = tanhf(z0[2]), o0 = tanhf(z0[3]);
        float i1 = tanhf(z1[0]), f1 = tanhf(z1[1]), g1 = tanhf(z1[2]), o1 = tanhf(z1[3]);
        float cn0 = f0 * c0 + i0 * g0;
        float cn1 = f1 * c1 + i1 * g1;
        float hn0 = o0 * tanhf(cn0);
        float hn1 = o1 * tanhf(cn1);
        if (m) { c0 = cn0; h0 = hn0; c1 = cn1; h1 = hn1; }

        *(float2*)(g_h + (((s & 1) * 2 + dir) * BB + gb) * UU + u0 + uu) =
            make_float2(h0, h1);
        *(float2*)(out + (((size_t)(gb * TT + t)) << 10) + (dir << 9) + u0 + uu) =
            make_float2(h0, h1);
        if (dir && s == TT - 1)
            *(float2*)(out + (size_t)BB * TT * 1024 + gb * UU + u0 + uu) =
                make_float2(h0, h1);

        __syncthreads();
        if (s < TT - 1) {
            if (tid == 0) {
                asm volatile("red.release.gpu.add.u32 [%0], 1;"
                             :: "l"(&g_bar[s]) : "memory");
                unsigned cnt;
                do {
                    asm volatile("ld.acquire.gpu.u32 %0, [%1];"
                                 : "=r"(cnt) : "l"(&g_bar[s]) : "memory");
                } while (cnt < NBLK);
            }
            __syncthreads();
        }
    }
}

extern "C" void kernel_launch(void* const* d_in, const int* in_sizes, int n_in,
                              void* d_out, int out_size) {
    const int*   x   = (const int*)d_in[0];
    const float* emb = (const float*)d_in[1];
    const float* W_f = (const float*)d_in[2];
    const float* R_f = (const float*)d_in[3];
    const float* b_f = (const float*)d_in[4];
    const float* W_b = (const float*)d_in[5];
    const float* R_b = (const float*)d_in[6];
    const float* b_b = (const float*)d_in[7];
    float* out = (float*)d_out;

    static bool attr_set = false;
    if (!attr_set) {
        cudaFuncSetAttribute(scan_kernel,
                             cudaFuncAttributeMaxDynamicSharedMemorySize, SMEM_SCAN);
        attr_set = true;
    }

    reset_kernel<<<1, TT>>>();
    dim3 gx(GG / 128, (TT * BB) / 128, 2);
    xproj_kernel<<<gx, 256>>>(x, emb, W_f, b_f, W_b, b_b);
    scan_kernel<<<NBLK, 256, SMEM_SCAN>>>(x, R_f, R_b, out);
}

// round 6
// speedup vs baseline: 1.0711x; 1.0271x over previous
#include <cuda_runtime.h>
#include <cuda_bf16.h>
#include <cstdint>
#include <cstddef>

typedef unsigned int u32;
typedef unsigned long long u64;

#define TT 256
#define NBLK 128

// ---- scan smem layout (bytes) ----
#define HS_OFF 0          /* h stacked hi/lo: 128 rows x 520 bf16 (1040 B/row) */
#define BH_OFF 133120     /* R_hi: 32 x 520 bf16 */
#define BL_OFF 166400     /* R_lo: 32 x 520 bf16 */
#define ZB_OFF 199680     /* z partials: 128 x 36 f32 */
#define SM_SCAN 218112

// ---- xproj smem layout ----
#define AH_OFF 0          /* emb hi: 128 x 264 bf16 (528 B/row) */
#define AL_OFF 67584
#define WH_OFF 135168     /* W hi: 64 x 264 bf16 */
#define WL_OFF 168960
#define BIAS_OFF 202752
#define TOKS_OFF 203776
#define SM_XP 204288

// Device-global scratch (allocation-guard safe)
__device__ float          g_xproj[(size_t)2 * TT * 64 * 2048];  // [dir][t*64+b][2048]
__device__ __nv_bfloat16  g_hbf[2 * 2 * 128 * 512];             // [par][dir][hi0-63|lo64-127][512]
__device__ unsigned       g_bar[TT];

__global__ void reset_kernel() { g_bar[threadIdx.x] = 0u; }

__device__ __forceinline__ u32 packbf(float a, float b) {
    __nv_bfloat162 t = __floats2bfloat162_rn(a, b);
    return *reinterpret_cast<u32*>(&t);
}
__device__ __forceinline__ uint4 ldg_cg4(const void* p) {
    uint4 v;
    asm volatile("ld.global.cg.v4.u32 {%0,%1,%2,%3}, [%4];"
                 : "=r"(v.x), "=r"(v.y), "=r"(v.z), "=r"(v.w) : "l"(p));
    return v;
}

#define MMA(d, a, b0_, b1_) \
    asm volatile( \
        "mma.sync.aligned.m16n8k16.row.col.f32.bf16.bf16.f32 " \
        "{%0,%1,%2,%3},{%4,%5,%6,%7},{%8,%9},{%0,%1,%2,%3};" \
        : "+f"((d)[0]), "+f"((d)[1]), "+f"((d)[2]), "+f"((d)[3]) \
        : "r"((a)[0]), "r"((a)[1]), "r"((a)[2]), "r"((a)[3]), \
          "r"(b0_), "r"(b1_))

// ---------------------------------------------------------------------------
// x_proj[dir][t*64+b][g] = emb[x[b,t]] @ W_dir + b_dir  via warp MMA.
// CTA: 128 token rows x 256 cols (4 n-tiles of 64), K=256, hi/lo 3-pass.
// ---------------------------------------------------------------------------
__global__ void __launch_bounds__(128, 1) xproj_kernel(
    const int* __restrict__ x, const float* __restrict__ emb,
    const float* __restrict__ W_f, const float* __restrict__ b_f,
    const float* __restrict__ W_b, const float* __restrict__ b_b)
{
    extern __shared__ char sp[];
    const int tid = threadIdx.x;
    const int warp = tid >> 5, lane = tid & 31;
    const int qr = lane >> 2, qc = lane & 3;
    const int dir = blockIdx.z;
    const int m0  = blockIdx.y << 7;
    const int ng  = blockIdx.x;                 // 256-col group
    const float* Wm = dir ? W_b : W_f;
    const float* bs = dir ? b_b : b_f;

    float* sbias = (float*)(sp + BIAS_OFF);
    int*   toks  = (int*)(sp + TOKS_OFF);

    {
        int r = m0 + tid;
        toks[tid] = x[(r & 63) * TT + (r >> 6)];
    }
    for (int i = tid; i < 256; i += 128) sbias[i] = bs[(ng << 8) + i];
    __syncthreads();

    // Stage A hi/lo: row-major [128][264] bf16
    #pragma unroll 4
    for (int it = 0; it < 32; it++) {
        int c = (it << 7) + tid;
        int row = c >> 5, q = c & 31;
        const float* e = emb + (size_t)toks[row] * 256 + (q << 3);
        float4 v0 = *(const float4*)e;
        float4 v1 = *(const float4*)(e + 4);
        float a[8] = {v0.x, v0.y, v0.z, v0.w, v1.x, v1.y, v1.z, v1.w};
        u32 hi[4], lo[4];
        #pragma unroll
        for (int p = 0; p < 4; p++) {
            float x0 = a[2 * p], x1 = a[2 * p + 1];
            __nv_bfloat16 h0 = __float2bfloat16(x0), h1 = __float2bfloat16(x1);
            hi[p] = ((u32)*(unsigned short*)&h1 << 16) | *(unsigned short*)&h0;
            lo[p] = packbf(x0 - __bfloat162float(h0), x1 - __bfloat162float(h1));
        }
        *(uint4*)(sp + AH_OFF + row * 528 + q * 16) = make_uint4(hi[0], hi[1], hi[2], hi[3]);
        *(uint4*)(sp + AL_OFF + row * 528 + q * 16) = make_uint4(lo[0], lo[1], lo[2], lo[3]);
    }

    float* gx = g_xproj + (size_t)dir * TT * 64 * 2048;
    const int rA = (warp << 5) + qr;
    const char* pA0 = sp + AH_OFF + rA * 528 + qc * 4;
    const char* pA1 = sp + AL_OFF + rA * 528 + qc * 4;

    for (int nt = 0; nt < 4; nt++) {
        const int ncol0 = (ng << 8) + (nt << 6);
        __syncthreads();
        // Stage W tile hi/lo: [64][264] bf16
        for (int i = tid; i < 64 * 256; i += 128) {
            int n = i & 63, k = i >> 6;
            float v = Wm[(size_t)k * 2048 + ncol0 + n];
            __nv_bfloat16 hb = __float2bfloat16(v);
            *(__nv_bfloat16*)(sp + WH_OFF + n * 528 + k * 2) = hb;
            *(__nv_bfloat16*)(sp + WL_OFF + n * 528 + k * 2) =
                __float2bfloat16(v - __bfloat162float(hb));
        }
        __syncthreads();

        float acc[2][8][4] = {};
        const char* pBh = sp + WH_OFF + qr * 528 + qc * 4;
        const char* pBl = sp + WL_OFF + qr * 528 + qc * 4;
        #pragma unroll 2
        for (int kk = 0; kk < 16; kk++) {
            u32 ah[2][4], al[2][4];
            #pragma unroll
            for (int mi = 0; mi < 2; mi++) {
                const u32* A = (const u32*)(pA0 + mi * 16 * 528 + kk * 32);
                ah[mi][0] = A[0]; ah[mi][1] = A[8 * 132]; ah[mi][2] = A[4]; ah[mi][3] = A[8 * 132 + 4];
                const u32* B = (const u32*)(pA1 + mi * 16 * 528 + kk * 32);
                al[mi][0] = B[0]; al[mi][1] = B[8 * 132]; al[mi][2] = B[4]; al[mi][3] = B[8 * 132 + 4];
            }
            #pragma unroll
            for (int ni = 0; ni < 8; ni++) {
                const u32* Bh = (const u32*)(pBh + ni * 8 * 528 + kk * 32);
                u32 bh0 = Bh[0], bh1 = Bh[4];
                const u32* Bl = (const u32*)(pBl + ni * 8 * 528 + kk * 32);
                u32 bl0 = Bl[0], bl1 = Bl[4];
                #pragma unroll
                for (int mi = 0; mi < 2; mi++) {
                    MMA(acc[mi][ni], ah[mi], bh0, bh1);
                    MMA(acc[mi][ni], ah[mi], bl0, bl1);
                    MMA(acc[mi][ni], al[mi], bh0, bh1);
                }
            }
        }

        // Epilogue: bias + direct global stores (float2 per frag row)
        #pragma unroll
        for (int mi = 0; mi < 2; mi++) {
            int rl = (warp << 5) + (mi << 4) + qr;
            float* o0 = gx + (size_t)(m0 + rl) * 2048 + ncol0;
            float* o1 = gx + (size_t)(m0 + rl + 8) * 2048 + ncol0;
            #pragma unroll
            for (int ni = 0; ni < 8; ni++) {
                int cl = (ni << 3) + (qc << 1);
                float b0 = sbias[(nt << 6) + cl], b1 = sbias[(nt << 6) + cl + 1];
                *(float2*)(o0 + cl) = make_float2(acc[mi][ni][0] + b0, acc[mi][ni][1] + b1);
                *(float2*)(o1 + cl) = make_float2(acc[mi][ni][2] + b0, acc[mi][ni][3] + b1);
            }
        }
    }
}

// ---------------------------------------------------------------------------
// Persistent bidirectional LSTM scan via warp MMA.
// 128 CTAs x 128 thr; CTA = (dir, 8 units -> N=32 cols n = uu*4+gate).
// A = [h_hi;h_lo] 128x512 bf16; B passes R_hi,R_lo accumulate into one D;
// z[b][n] = D[b][n] + D[64+b][n]  (exact hi/lo recombination).
// ---------------------------------------------------------------------------
__global__ void __launch_bounds__(128, 1) scan_kernel(
    const int* __restrict__ x,
    const float* __restrict__ R_f,
    const float* __restrict__ R_b,
    float* __restrict__ out)
{
    extern __shared__ char sp[];
    const int tid = threadIdx.x;
    const int warp = tid >> 5, lane = tid & 31;
    const int qr = lane >> 2, qc = lane & 3;
    const int dir = blockIdx.x >> 6;
    const int u0  = (blockIdx.x & 63) << 3;
    const float* Rm = dir ? R_b : R_f;
    const float* xp = g_xproj + (size_t)dir * TT * 64 * 2048;
    float* zr = (float*)(sp + ZB_OFF);

    // Persistent B: row n <- R[:, (n&3)*512 + u0 + (n>>2)], hi/lo split
    for (int i = tid; i < 32 * 512; i += 128) {
        int n = i & 31, k = i >> 5;
        float v = Rm[(size_t)k * 2048 + (n & 3) * 512 + u0 + (n >> 2)];
        __nv_bfloat16 hb = __float2bfloat16(v);
        *(__nv_bfloat16*)(sp + BH_OFF + n * 1040 + k * 2) = hb;
        *(__nv_bfloat16*)(sp + BL_OFF + n * 1040 + k * 2) =
            __float2bfloat16(v - __bfloat162float(hb));
    }

    const int rA = (warp << 5) + qr;
    const char* pA  = sp + HS_OFF + rA * 1040 + qc * 4;
    const char* pBh = sp + BH_OFF + qr * 1040 + qc * 4;
    const char* pBl = sp + BL_OFF + qr * 1040 + qc * 4;

    const int b  = tid & 63;
    const int uh = tid >> 6;
    float cst[4] = {0.f, 0.f, 0.f, 0.f};
    float hcur[4] = {0.f, 0.f, 0.f, 0.f};

    __syncthreads();

    for (int s = 0; s < TT; s++) {
        const int t = dir ? (TT - 1 - s) : s;
        const int m = x[b * TT + t] != 0;
        const float* xzp = xp + ((size_t)(t * 64 + b)) * 2048 + u0 + (uh << 2);
        float xz[4][4];
        *(float4*)&xz[0][0] = *(const float4*)(xzp);
        *(float4*)&xz[1][0] = *(const float4*)(xzp + 512);
        *(float4*)&xz[2][0] = *(const float4*)(xzp + 1024);
        *(float4*)&xz[3][0] = *(const float4*)(xzp + 1536);

        if (s) {
            // Stage A = [h_hi; h_lo] (parity (s-1)&1) into smem
            const char* hb = (const char*)(g_hbf +
                ((size_t)(((s - 1) & 1) * 2 + dir) * 128) * 512);
            #pragma unroll 8
            for (int it = 0; it < 64; it++) {
                int f = (it << 7) + tid;
                uint4 v = ldg_cg4(hb + f * 16);
                *(uint4*)(sp + HS_OFF + (f >> 6) * 1040 + (f & 63) * 16) = v;
            }
            __syncthreads();

            float acc[2][4][4] = {};
            #pragma unroll 2
            for (int kk = 0; kk < 32; kk++) {
                u32 a0[4], a1[4];
                {
                    const u32* A = (const u32*)(pA + kk * 32);
                    a0[0] = A[0]; a0[1] = A[8 * 260]; a0[2] = A[4]; a0[3] = A[8 * 260 + 4];
                    const u32* B = (const u32*)(pA + 16 * 1040 + kk * 32);
                    a1[0] = B[0]; a1[1] = B[8 * 260]; a1[2] = B[4]; a1[3] = B[8 * 260 + 4];
                }
                #pragma unroll
                for (int ni = 0; ni < 4; ni++) {
                    const u32* Bh = (const u32*)(pBh + ni * 8 * 1040 + kk * 32);
                    u32 bh0 = Bh[0], bh1 = Bh[4];
                    const u32* Bl = (const u32*)(pBl + ni * 8 * 1040 + kk * 32);
                    u32 bl0 = Bl[0], bl1 = Bl[4];
                    MMA(acc[0][ni], a0, bh0, bh1);
                    MMA(acc[0][ni], a0, bl0, bl1);
                    MMA(acc[1][ni], a1, bh0, bh1);
                    MMA(acc[1][ni], a1, bl0, bl1);
                }
            }
            __syncthreads();   // zbuf region idle; also fences hs reads done
            #pragma unroll
            for (int mi = 0; mi < 2; mi++) {
                int row = (warp << 5) + (mi << 4) + qr;
                #pragma unroll
                for (int ni = 0; ni < 4; ni++) {
                    int col = (ni << 3) + (qc << 1);
                    *(float2*)(zr + row * 36 + col) =
                        make_float2(acc[mi][ni][0], acc[mi][ni][1]);
                    *(float2*)(zr + (row + 8) * 36 + col) =
                        make_float2(acc[mi][ni][2], acc[mi][ni][3]);
                }
            }
            __syncthreads();
        }

        float h4[4];
        #pragma unroll
        for (int j = 0; j < 4; j++) {
            float zi = xz[0][j], zf = xz[1][j], zg = xz[2][j], zo = xz[3][j];
            if (s) {
                float4 vh = *(const float4*)(zr + b * 36 + (uh << 4) + (j << 2));
                float4 vl = *(const float4*)(zr + (64 + b) * 36 + (uh << 4) + (j << 2));
                zi += vh.x + vl.x; zf += vh.y + vl.y;
                zg += vh.z + vl.z; zo += vh.w + vl.w;
            }
            float iv = tanhf(zi), fv = tanhf(zf), gv = tanhf(zg), ov = tanhf(zo);
            float cn = fv * cst[j] + iv * gv;
            float hn = ov * tanhf(cn);
            if (m) { cst[j] = cn; hcur[j] = hn; }
            h4[j] = hcur[j];
        }

        *(float4*)(out + (((size_t)(b * TT + t)) << 10) + (dir << 9) + u0 + (uh << 2)) =
            *(float4*)h4;
        if (dir && s == TT - 1)
            *(float4*)(out + (size_t)64 * TT * 1024 + (size_t)b * 512 + u0 + (uh << 2)) =
                *(float4*)h4;
        {
            __nv_bfloat16 b0 = __float2bfloat16(h4[0]), b1 = __float2bfloat16(h4[1]);
            __nv_bfloat16 b2 = __float2bfloat16(h4[2]), b3 = __float2bfloat16(h4[3]);
            u32 p01 = ((u32)*(unsigned short*)&b1 << 16) | *(unsigned short*)&b0;
            u32 p23 = ((u32)*(unsigned short*)&b3 << 16) | *(unsigned short*)&b2;
            u32 q01 = packbf(h4[0] - __bfloat162float(b0), h4[1] - __bfloat162float(b1));
            u32 q23 = packbf(h4[2] - __bfloat162float(b2), h4[3] - __bfloat162float(b3));
            __nv_bfloat16* hb = g_hbf + ((size_t)((s & 1) * 2 + dir) * 128) * 512;
            *(uint2*)(hb + (size_t)b * 512 + u0 + (uh << 2))        = make_uint2(p01, p23);
            *(uint2*)(hb + (size_t)(64 + b) * 512 + u0 + (uh << 2)) = make_uint2(q01, q23);
        }

        __syncthreads();
        if (s < TT - 1) {
            if (tid == 0) {
                asm volatile("red.release.gpu.add.u32 [%0], 1;" :: "l"(&g_bar[s]) : "memory");
                unsigned cnt;
                do {
                    asm volatile("ld.acquire.gpu.u32 %0, [%1];"
                                 : "=r"(cnt) : "l"(&g_bar[s]) : "memory");
                } while (cnt < NBLK);
            }
            __syncthreads();
        }
    }
}

extern "C" void kernel_launch(void* const* d_in, const int* in_sizes, int n_in,
                              void* d_out, int out_size) {
    const int*   x   = (const int*)d_in[0];
    const float* emb = (const float*)d_in[1];
    const float* W_f = (const float*)d_in[2];
    const float* R_f = (const float*)d_in[3];
    const float* b_f = (const float*)d_in[4];
    const float* W_b = (const float*)d_in[5];
    const float* R_b = (const float*)d_in[6];
    const float* b_b = (const float*)d_in[7];
    float* out = (float*)d_out;

    cudaFuncSetAttribute(xproj_kernel, cudaFuncAttributeMaxDynamicSharedMemorySize, SM_XP);
    cudaFuncSetAttribute(scan_kernel,  cudaFuncAttributeMaxDynamicSharedMemorySize, SM_SCAN);

    reset_kernel<<<1, TT>>>();
    xproj_kernel<<<dim3(8, 128, 2), 128, SM_XP>>>(x, emb, W_f, b_f, W_b, b_b);
    scan_kernel<<<NBLK, 128, SM_SCAN>>>(x, R_f, R_b, out);
}

// round 8
// speedup vs baseline: 1.5675x; 1.4635x over previous
#include <cuda_runtime.h>
#include <cuda_bf16.h>
#include <cstdint>
#include <cstddef>

typedef unsigned int u32;
typedef unsigned long long u64;

#define TT 256
#define NBLK 128

// ---- scan smem layout (bytes) ----
#define HS_OFF 0          /* h stacked hi/lo: 128 rows x 520 bf16 (1040 B/row) */
#define BH_OFF 133120     /* R_hi: 32 rows([n]) x 520 bf16 */
#define BL_OFF 166400
#define ZB_OFF 199680     /* z: 128 x 36 f32 */
#define MB_OFF 218112     /* mask bitmap: 512 u32 */
#define SM_SCAN 220160

// ---- xproj smem layout ----
#define AH_OFF 0          /* A hi: 128 rows x 264 bf16 (528 B/row) */
#define AL_OFF 67584
#define WH_OFF 135168     /* W hi: 64 rows([n]) x 264 bf16 */
#define WL_OFF 168960
#define BIAS_OFF 202752
#define SM_XP 204800

// Device-global scratch (allocation-guard safe)
__device__ float          g_xproj[(size_t)2 * TT * 64 * 2048];  // [dir][t*64+b][2048]
__device__ __nv_bfloat16  g_Ah[(size_t)16384 * 256];            // emb gather hi, row r=t*64+b
__device__ __nv_bfloat16  g_Al[(size_t)16384 * 256];
__device__ __nv_bfloat16  g_Wth[(size_t)2 * 2048 * 256];        // W^T hi: [dir][n][k]
__device__ __nv_bfloat16  g_Wtl[(size_t)2 * 2048 * 256];
__device__ __nv_bfloat16  g_hbf[2 * 2 * 128 * 512];             // [par][dir][hi0-63|lo64-127][512]
__device__ unsigned       g_bar[TT];

__device__ __forceinline__ u32 smem_u32(const void* p) {
    u32 a;
    asm("{ .reg .u64 t; cvta.to.shared.u64 t, %1; cvt.u32.u64 %0, t; }" : "=r"(a) : "l"(p));
    return a;
}
__device__ __forceinline__ u32 packbf(float a, float b) {
    __nv_bfloat162 t = __floats2bfloat162_rn(a, b);
    return *reinterpret_cast<u32*>(&t);
}
__device__ __forceinline__ uint4 ldg_cg4(const void* p) {
    uint4 v;
    asm volatile("ld.global.cg.v4.u32 {%0,%1,%2,%3}, [%4];"
                 : "=r"(v.x), "=r"(v.y), "=r"(v.z), "=r"(v.w) : "l"(p));
    return v;
}

#define MMA(d, a, b0_, b1_) \
    asm volatile( \
        "mma.sync.aligned.m16n8k16.row.col.f32.bf16.bf16.f32 " \
        "{%0,%1,%2,%3},{%4,%5,%6,%7},{%8,%9},{%0,%1,%2,%3};" \
        : "+f"((d)[0]), "+f"((d)[1]), "+f"((d)[2]), "+f"((d)[3]) \
        : "r"((a)[0]), "r"((a)[1]), "r"((a)[2]), "r"((a)[3]), \
          "r"(b0_), "r"(b1_))

#define LDSM4(r, a) \
    asm volatile("ldmatrix.sync.aligned.m8n8.x4.shared.b16 {%0,%1,%2,%3}, [%4];" \
        : "=r"((r)[0]), "=r"((r)[1]), "=r"((r)[2]), "=r"((r)[3]) : "r"(a))

// ---------------------------------------------------------------------------
// Prep: one-time bf16 hi/lo conversion of gathered emb (A) and W^T.
// ---------------------------------------------------------------------------
__global__ void __launch_bounds__(256) prep_kernel(
    const int* __restrict__ x, const float* __restrict__ emb,
    const float* __restrict__ W_f, const float* __restrict__ W_b)
{
    const size_t NA = (size_t)16384 * 256;
    const size_t NW = (size_t)2 * 2048 * 256;
    for (size_t i = (size_t)blockIdx.x * 256 + threadIdx.x; i < NA + NW;
         i += (size_t)gridDim.x * 256) {
        if (i < NA) {
            int r = (int)(i >> 8), k = (int)(i & 255);
            int tok = x[(r & 63) * TT + (r >> 6)];
            float v = emb[(size_t)tok * 256 + k];
            __nv_bfloat16 hb = __float2bfloat16(v);
            g_Ah[i] = hb;
            g_Al[i] = __float2bfloat16(v - __bfloat162float(hb));
        } else {
            size_t j = i - NA;
            int dir = (int)(j >> 19);
            int k = (int)((j >> 11) & 255), n = (int)(j & 2047);
            const float* Wm = dir ? W_b : W_f;
            float v = Wm[(size_t)k * 2048 + n];
            __nv_bfloat16 hb = __float2bfloat16(v);
            size_t o = ((size_t)dir * 2048 + n) * 256 + k;
            g_Wth[o] = hb;
            g_Wtl[o] = __float2bfloat16(v - __bfloat162float(hb));
        }
    }
}

// ---------------------------------------------------------------------------
// x_proj bf16 GEMM (pre-converted inputs). CTA: 128 rows x 256 cols.
// 128 thr / 4 warps; warp = 32 rows (2 m-tiles); ldmatrix fragments.
// ---------------------------------------------------------------------------
__global__ void __launch_bounds__(128, 1) xproj_kernel(
    const float* __restrict__ b_f, const float* __restrict__ b_b)
{
    extern __shared__ char sp[];
    const int tid = threadIdx.x;
    const int warp = tid >> 5, lane = tid & 31;
    const int qr = lane >> 2, qc = lane & 3;
    const int dir = blockIdx.z;
    const int m0  = blockIdx.y << 7;
    const int ng  = blockIdx.x;
    const float* bs = dir ? b_b : b_f;
    float* sbias = (float*)(sp + BIAS_OFF);

    for (int i = tid; i < 256; i += 128) sbias[i] = bs[(ng << 8) + i];

    // Stage A hi/lo rows m0..m0+127 (512 B each) into [128][528]
    {
        const uint4* sh = (const uint4*)(g_Ah + (size_t)m0 * 256);
        const uint4* sl = (const uint4*)(g_Al + (size_t)m0 * 256);
        #pragma unroll 8
        for (int it = 0; it < 32; it++) {
            int f = (it << 7) + tid;
            int row = f >> 5, c = f & 31;
            *(uint4*)(sp + AH_OFF + row * 528 + c * 16) = sh[f];
            *(uint4*)(sp + AL_OFF + row * 528 + c * 16) = sl[f];
        }
    }

    const u32 spb = smem_u32(sp);
    u32 aAh[2], aAl[2];
    #pragma unroll
    for (int mi = 0; mi < 2; mi++) {
        int row = (warp << 5) + (mi << 4) + (lane & 15);
        aAh[mi] = spb + AH_OFF + row * 528 + (lane >> 4) * 16;
        aAl[mi] = spb + AL_OFF + row * 528 + (lane >> 4) * 16;
    }
    const int brow = (lane & 7) + 8 * (lane >> 4);
    const u32 koff = ((lane >> 3) & 1) * 16;
    float* gx = g_xproj + (size_t)dir * TT * 64 * 2048;

    for (int nt = 0; nt < 4; nt++) {
        const int ncol0 = (ng << 8) + (nt << 6);
        __syncthreads();
        // Stage W^T rows ncol0..+63 (512 B each) into [64][528]
        {
            const uint4* wh = (const uint4*)(g_Wth + ((size_t)dir * 2048 + ncol0) * 256);
            const uint4* wl = (const uint4*)(g_Wtl + ((size_t)dir * 2048 + ncol0) * 256);
            #pragma unroll 4
            for (int it = 0; it < 16; it++) {
                int f = (it << 7) + tid;
                int row = f >> 5, c = f & 31;
                *(uint4*)(sp + WH_OFF + row * 528 + c * 16) = wh[f];
                *(uint4*)(sp + WL_OFF + row * 528 + c * 16) = wl[f];
            }
        }
        __syncthreads();

        float acc[2][8][4] = {};
        #pragma unroll 1
        for (int kk = 0; kk < 16; kk++) {
            u32 ah[2][4], al[2][4];
            LDSM4(ah[0], aAh[0] + kk * 32);
            LDSM4(ah[1], aAh[1] + kk * 32);
            LDSM4(al[0], aAl[0] + kk * 32);
            LDSM4(al[1], aAl[1] + kk * 32);
            #pragma unroll
            for (int p = 0; p < 4; p++) {
                u32 bh[4], bl[4];
                u32 ab = spb + (brow + (p << 4)) * 528 + koff + kk * 32;
                LDSM4(bh, ab + WH_OFF);
                LDSM4(bl, ab + WL_OFF);
                #pragma unroll
                for (int q = 0; q < 2; q++) {
                    int ni = (p << 1) + q;
                    #pragma unroll
                    for (int mi = 0; mi < 2; mi++) {
                        MMA(acc[mi][ni], ah[mi], bh[2 * q], bh[2 * q + 1]);
                        MMA(acc[mi][ni], ah[mi], bl[2 * q], bl[2 * q + 1]);
                        MMA(acc[mi][ni], al[mi], bh[2 * q], bh[2 * q + 1]);
                    }
                }
            }
        }

        #pragma unroll
        for (int mi = 0; mi < 2; mi++) {
            int rl = (warp << 5) + (mi << 4) + qr;
            float* o0 = gx + (size_t)(m0 + rl) * 2048 + ncol0;
            float* o1 = gx + (size_t)(m0 + rl + 8) * 2048 + ncol0;
            #pragma unroll
            for (int ni = 0; ni < 8; ni++) {
                int cl = (ni << 3) + (qc << 1);
                float b0 = sbias[(nt << 6) + cl], b1 = sbias[(nt << 6) + cl + 1];
                *(float2*)(o0 + cl) = make_float2(acc[mi][ni][0] + b0, acc[mi][ni][1] + b1);
                *(float2*)(o1 + cl) = make_float2(acc[mi][ni][2] + b0, acc[mi][ni][3] + b1);
            }
        }
    }
}

// ---------------------------------------------------------------------------
// Persistent bidirectional LSTM scan. 128 CTAs x 256 thr (8 warps).
// CTA = (dir, 8 units -> N=32 cols n = uu*4+gate). Warp w = m-tile rows
// 16w..16w+15 of stacked A=[h_hi;h_lo] (128x512 bf16). Two B passes
// (R_hi, R_lo) accumulate into one D; z[b] = D[b] + D[64+b].
// ---------------------------------------------------------------------------
__global__ void __launch_bounds__(256, 1) scan_kernel(
    const int* __restrict__ x,
    const float* __restrict__ R_f,
    const float* __restrict__ R_b,
    float* __restrict__ out)
{
    extern __shared__ char sp[];
    const int tid = threadIdx.x;
    const int warp = tid >> 5, lane = tid & 31;
    const int qr = lane >> 2, qc = lane & 3;
    const int dir = blockIdx.x >> 6;
    const int u0  = (blockIdx.x & 63) << 3;
    const float* Rm = dir ? R_b : R_f;
    const float* xp = g_xproj + (size_t)dir * TT * 64 * 2048;
    float* zr = (float*)(sp + ZB_OFF);
    u32* mbits = (u32*)(sp + MB_OFF);

    // Persistent B: row n <- R[:, (n&3)*512 + u0 + (n>>2)], hi/lo split
    for (int i = tid; i < 32 * 512; i += 256) {
        int n = i & 31, k = i >> 5;
        float v = Rm[(size_t)k * 2048 + (n & 3) * 512 + u0 + (n >> 2)];
        __nv_bfloat16 hb = __float2bfloat16(v);
        *(__nv_bfloat16*)(sp + BH_OFF + n * 1040 + k * 2) = hb;
        *(__nv_bfloat16*)(sp + BL_OFF + n * 1040 + k * 2) =
            __float2bfloat16(v - __bfloat162float(hb));
    }
    // Mask bitmap: word w = t*2 + (b>>5)
    for (int w = tid; w < 512; w += 256) {
        int t = w >> 1, h32 = (w & 1) << 5;
        u32 bits = 0;
        #pragma unroll 8
        for (int j = 0; j < 32; j++)
            bits |= (u32)(x[(h32 + j) * TT + t] != 0) << j;
        mbits[w] = bits;
    }

    const u32 spb = smem_u32(sp);
    const u32 aA = spb + HS_OFF + ((warp << 4) + (lane & 15)) * 1040 + (lane >> 4) * 16;
    const int brow = (lane & 7) + 8 * (lane >> 4);
    const u32 koff = ((lane >> 3) & 1) * 16;

    const int ue = tid & 3;          // unit pair: units 2ue, 2ue+1
    const int be = tid >> 2;         // batch 0..63
    float cst[2] = {0.f, 0.f}, hcur[2] = {0.f, 0.f};

    __syncthreads();

    for (int s = 0; s < TT; s++) {
        const int t = dir ? (TT - 1 - s) : s;
        const int m = (mbits[(t << 1) + (be >> 5)] >> (be & 31)) & 1;
        const float* xzp = xp + ((size_t)(t * 64 + be)) * 2048 + u0 + (ue << 1);
        float2 xg[4];
        #pragma unroll
        for (int g = 0; g < 4; g++) xg[g] = *(const float2*)(xzp + (g << 9));

        if (s) {
            // Stage A = [h_hi; h_lo] (parity (s-1)&1): 128 rows x 64 uint4
            const char* hb = (const char*)(g_hbf +
                ((size_t)(((s - 1) & 1) * 2 + dir) * 128) * 512);
            #pragma unroll 8
            for (int it = 0; it < 32; it++) {
                int f = (it << 8) + tid;
                uint4 v = ldg_cg4(hb + f * 16);
                *(uint4*)(sp + HS_OFF + (f >> 6) * 1040 + (f & 63) * 16) = v;
            }
            __syncthreads();

            float acc[4][4] = {};
            #pragma unroll 1
            for (int kk = 0; kk < 32; kk++) {
                u32 a[4];
                LDSM4(a, aA + kk * 32);
                #pragma unroll
                for (int p = 0; p < 2; p++) {
                    u32 bh[4], bl[4];
                    u32 ab = spb + (brow + (p << 4)) * 1040 + koff + kk * 32;
                    LDSM4(bh, ab + BH_OFF);
                    LDSM4(bl, ab + BL_OFF);
                    #pragma unroll
                    for (int q = 0; q < 2; q++) {
                        int ni = (p << 1) + q;
                        MMA(acc[ni], a, bh[2 * q], bh[2 * q + 1]);
                        MMA(acc[ni], a, bl[2 * q], bl[2 * q + 1]);
                    }
                }
            }
            // Each warp owns distinct D rows: write zr directly
            {
                int row0 = (warp << 4) + qr;
                #pragma unroll
                for (int ni = 0; ni < 4; ni++) {
                    int col = (ni << 3) + (qc << 1);
                    *(float2*)(zr + row0 * 36 + col) = make_float2(acc[ni][0], acc[ni][1]);
                    *(float2*)(zr + (row0 + 8) * 36 + col) = make_float2(acc[ni][2], acc[ni][3]);
                }
            }
            __syncthreads();
        }

        float h2[2];
        #pragma unroll
        for (int j = 0; j < 2; j++) {
            int cb = ((ue << 1) + j) << 2;
            float zi = (j ? xg[0].y : xg[0].x), zf = (j ? xg[1].y : xg[1].x);
            float zg = (j ? xg[2].y : xg[2].x), zo = (j ? xg[3].y : xg[3].x);
            if (s) {
                float4 vh = *(const float4*)(zr + be * 36 + cb);
                float4 vl = *(const float4*)(zr + (64 + be) * 36 + cb);
                zi += vh.x + vl.x; zf += vh.y + vl.y;
                zg += vh.z + vl.z; zo += vh.w + vl.w;
            }
            float iv = tanhf(zi), fv = tanhf(zf), gv = tanhf(zg), ov = tanhf(zo);
            float cn = fv * cst[j] + iv * gv;
            float hn = ov * tanhf(cn);
            if (m) { cst[j] = cn; hcur[j] = hn; }
            h2[j] = hcur[j];
        }

        *(float2*)(out + (((size_t)(be * TT + t)) << 10) + (dir << 9) + u0 + (ue << 1)) =
            make_float2(h2[0], h2[1]);
        if (dir && s == TT - 1)
            *(float2*)(out + (size_t)64 * TT * 1024 + (size_t)be * 512 + u0 + (ue << 1)) =
                make_float2(h2[0], h2[1]);
        {
            __nv_bfloat16 b0 = __float2bfloat16(h2[0]), b1 = __float2bfloat16(h2[1]);
            u32 hiw = ((u32)*(unsigned short*)&b1 << 16) | *(unsigned short*)&b0;
            u32 low = packbf(h2[0] - __bfloat162float(b0), h2[1] - __bfloat162float(b1));
            __nv_bfloat16* hb = g_hbf + ((size_t)((s & 1) * 2 + dir) * 128) * 512;
            *(u32*)(hb + (size_t)be * 512 + u0 + (ue << 1))        = hiw;
            *(u32*)(hb + (size_t)(64 + be) * 512 + u0 + (ue << 1)) = low;
        }

        __syncthreads();
        if (s < TT - 1) {
            if (tid == 0) {
                asm volatile("red.release.gpu.add.u32 [%0], 1;" :: "l"(&g_bar[s]) : "memory");
                unsigned cnt;
                do {
                    asm volatile("ld.acquire.gpu.u32 %0, [%1];"
                                 : "=r"(cnt) : "l"(&g_bar[s]) : "memory");
                } while (cnt < NBLK);
            }
            __syncthreads();
        }
    }

    // Self-reset barrier array for the next graph replay.
    __syncthreads();
    if (tid == 0) {
        asm volatile("red.release.gpu.add.u32 [%0], 1;" :: "l"(&g_bar[TT - 1]) : "memory");
        if (blockIdx.x == 0) {
            unsigned cnt;
            do {
                asm volatile("ld.acquire.gpu.u32 %0, [%1];"
                             : "=r"(cnt) : "l"(&g_bar[TT - 1]) : "memory");
            } while (cnt < NBLK);
            for (int i = 0; i < TT; i++) g_bar[i] = 0u;
        }
    }
}

extern "C" void kernel_launch(void* const* d_in, const int* in_sizes, int n_in,
                              void* d_out, int out_size) {
    const int*   x   = (const int*)d_in[0];
    const float* emb = (const float*)d_in[1];
    const float* W_f = (const float*)d_in[2];
    const float* R_f = (const float*)d_in[3];
    const float* b_f = (const float*)d_in[4];
    const float* W_b = (const float*)d_in[5];
    const float* R_b = (const float*)d_in[6];
    const float* b_b = (const float*)d_in[7];
    float* out = (float*)d_out;

    cudaFuncSetAttribute(xproj_kernel, cudaFuncAttributeMaxDynamicSharedMemorySize, SM_XP);
    cudaFuncSetAttribute(scan_kernel,  cudaFuncAttributeMaxDynamicSharedMemorySize, SM_SCAN);

    prep_kernel<<<2048, 256>>>(x, emb, W_f, W_b);
    xproj_kernel<<<dim3(8, 128, 2), 128, SM_XP>>>(b_f, b_b);
    scan_kernel<<<NBLK, 256, SM_SCAN>>>(x, R_f, R_b, out);
}